// round 16
// baseline (speedup 1.0000x reference)
#include <cuda_runtime.h>
#include <cuda_fp16.h>
#include <cstdint>

#define NNODES 50000
#define NEDGES 800000

#define MASK_WORDS 500000
#define MOFF_L1 0
#define MOFF_L2 200000
#define MOFF_L3 400000

// ---------------- device scratch (symbols ONLY ever touched in device code) --
__device__ __align__(16) int    g_mode;
__device__ __align__(16) int    g_deg_out[NNODES];
__device__ __align__(16) int    g_deg_in[NNODES];
__device__ __align__(16) int    g_fill[NNODES];
__device__ __align__(16) int    g_rowptr[NNODES + 1];
__device__ __align__(16) int    g_csr_src[NEDGES];
__device__ __align__(16) float  g_norm_src[NNODES];
__device__ __align__(16) float  g_norm_dst[NNODES];
__device__ __align__(16) float  g_agg[NNODES * 128];   // fp32 GEMM input
__device__ __align__(16) __half g_hh[NNODES * 128];    // fp16 gather operand
__device__ __align__(16) unsigned g_mask[MASK_WORDS];

// ---------------- f32x2 packed math ----------------
__device__ __forceinline__ unsigned long long pack2(float x, float y) {
    unsigned long long r;
    asm("mov.b64 %0, {%1, %2};" : "=l"(r) : "f"(x), "f"(y));
    return r;
}
__device__ __forceinline__ void unpack2(unsigned long long v, float& x, float& y) {
    asm("mov.b64 {%0, %1}, %2;" : "=f"(x), "=f"(y) : "l"(v));
}
__device__ __forceinline__ void fma2(unsigned long long& d,
                                     unsigned long long a, unsigned long long b) {
    asm("fma.rn.f32x2 %0, %1, %2, %0;" : "+l"(d) : "l"(a), "l"(b));
}

// ---------------- threefry-2x32 ----------------
__host__ __device__ __forceinline__ void tf2x32(unsigned k0, unsigned k1,
                                                unsigned x0, unsigned x1,
                                                unsigned& o0, unsigned& o1) {
    unsigned ks2 = k0 ^ k1 ^ 0x1BD11BDAu;
#define TF_R(r) do { x0 += x1; x1 = (x1 << (r)) | (x1 >> (32 - (r))); x1 ^= x0; } while (0)
    x0 += k0; x1 += k1;
    TF_R(13); TF_R(15); TF_R(26); TF_R(6);   x0 += k1;  x1 += ks2 + 1u;
    TF_R(17); TF_R(29); TF_R(16); TF_R(24);  x0 += ks2; x1 += k0 + 2u;
    TF_R(13); TF_R(15); TF_R(26); TF_R(6);   x0 += k0;  x1 += k1 + 3u;
    TF_R(17); TF_R(29); TF_R(16); TF_R(24);  x0 += k1;  x1 += ks2 + 4u;
    TF_R(13); TF_R(15); TF_R(26); TF_R(6);   x0 += ks2; x1 += k0 + 5u;
#undef TF_R
    o0 = x0; o1 = x1;
}

// ---------------- edge dtype detect + zero (fused) ----------------
__global__ void detect_zero_kernel(const void* src) {
    int i = blockIdx.x * blockDim.x + threadIdx.x;
    if (i < NNODES) { g_deg_out[i] = 0; g_deg_in[i] = 0; g_fill[i] = 0; }
    if (blockIdx.x == 0 && threadIdx.x == 0) {
        const unsigned* w = (const unsigned*)src;
        int odd_nonzero = 0, hi16 = 0;
        for (int k = 0; k < 256; k += 2) {
            if (w[k + 1] != 0u) odd_nonzero++;
            if (w[k] & 0xFFFF0000u) hi16++;
        }
        if (odd_nonzero == 0) g_mode = 1;
        else if (hi16 > 64)   g_mode = 2;
        else                  g_mode = 0;
    }
}

__device__ __forceinline__ int edge_val(const void* p, int i) {
    int v;
    if (g_mode == 1)      v = (int)((const long long*)p)[i];
    else if (g_mode == 2) v = (int)((const float*)p)[i];
    else                  v = ((const int*)p)[i];
    v = v < 0 ? 0 : v;
    return v >= NNODES ? NNODES - 1 : v;
}

// ---------------- preprocessing ----------------
__global__ void degrees_kernel(const void* src, const void* dst) {
    int e = blockIdx.x * blockDim.x + threadIdx.x;
    if (e < NEDGES) {
        atomicAdd(&g_deg_out[edge_val(src, e)], 1);
        atomicAdd(&g_deg_in[edge_val(dst, e)], 1);
    }
}

__global__ void norms_kernel() {
    int i = blockIdx.x * blockDim.x + threadIdx.x;
    if (i < NNODES) {
        float dO = (float)g_deg_out[i];
        float dI = (float)g_deg_in[i];
        g_norm_src[i] = rsqrtf(dO > 1.0f ? dO : 1.0f);
        g_norm_dst[i] = rsqrtf(dI > 1.0f ? dI : 1.0f);
    }
}

__global__ void scan_kernel() {
    __shared__ int warp_sums[32];
    __shared__ int s_carry;
    int t = threadIdx.x;
    int lane = t & 31, wid = t >> 5;
    if (t == 0) s_carry = 0;
    __syncthreads();
    for (int base = 0; base < NNODES; base += 1024) {
        int i = base + t;
        int v = (i < NNODES) ? g_deg_in[i] : 0;
        int val = v;
#pragma unroll
        for (int off = 1; off < 32; off <<= 1) {
            int n = __shfl_up_sync(0xFFFFFFFFu, val, off);
            if (lane >= off) val += n;
        }
        if (lane == 31) warp_sums[wid] = val;
        __syncthreads();
        if (wid == 0) {
            int s = warp_sums[lane];
#pragma unroll
            for (int off = 1; off < 32; off <<= 1) {
                int n = __shfl_up_sync(0xFFFFFFFFu, s, off);
                if (lane >= off) s += n;
            }
            warp_sums[lane] = s;
        }
        __syncthreads();
        int prefix = s_carry + (wid > 0 ? warp_sums[wid - 1] : 0);
        if (i < NNODES) g_rowptr[i] = prefix + val - v;
        __syncthreads();
        if (t == 0) s_carry += warp_sums[31];
        __syncthreads();
    }
    if (t == 0) g_rowptr[NNODES] = s_carry;
}

__global__ void scatter_kernel(const void* src, const void* dst) {
    int e = blockIdx.x * blockDim.x + threadIdx.x;
    if (e < NEDGES) {
        int d = edge_val(dst, e);
        int pos = g_rowptr[d] + atomicAdd(&g_fill[d], 1);
        if (pos >= 0 && pos < NEDGES) g_csr_src[pos] = edge_val(src, e);
    }
}

// ---------------- features fp32 -> fp16 ----------------
__global__ void f2h_kernel(const float* __restrict__ x) {
    int i = blockIdx.x * blockDim.x + threadIdx.x;   // over float4s
    if (i >= NNODES * 32) return;
    float4 v = ((const float4*)x)[i];
    __half2 p0 = __floats2half2_rn(v.x, v.y);
    __half2 p1 = __floats2half2_rn(v.z, v.w);
    unsigned long long u;
    asm("mov.b64 %0, {%1, %2};" : "=l"(u)
        : "r"(*(unsigned*)&p0), "r"(*(unsigned*)&p1));
    ((unsigned long long*)g_hh)[i] = u;
}

// ---------------- aggregation + fused dropout-mask generation --------------
// Warp per node. The threefry ALU work issues from other warps while gather
// warps stall on L2 (stall_long_scoreboard) -> mask generation rides free in
// the memory-stall shadow. NOUT = columns of the FOLLOWING gemm (mask shape).
template <int NOUT>
__global__ void aggregate_kernel(unsigned k0, unsigned k1, int moff) {
    int gtid = blockIdx.x * blockDim.x + threadIdx.x;
    int node = gtid >> 5;
    int lane = gtid & 31;
    if (node >= NNODES) return;

    // dropout mask for this node's output row: NOUT evals, 1 bit each,
    // assembled 32-at-a-time via ballot. idx = node*NOUT + w*32 + lane.
#pragma unroll
    for (int w = 0; w < NOUT / 32; w++) {
        unsigned idx = (unsigned)node * NOUT + w * 32 + lane;
        unsigned o0, o1;
        tf2x32(k0, k1, 0u, idx, o0, o1);
        unsigned bits = __ballot_sync(0xFFFFFFFFu, !((o0 ^ o1) >> 31));
        if (lane == 0) g_mask[moff + node * (NOUT / 32) + w] = bits;
    }

    const unsigned long long* h8 = (const unsigned long long*)g_hh;
    int beg = g_rowptr[node], end = g_rowptr[node + 1];
    float4 acc = make_float4(0.f, 0.f, 0.f, 0.f);
    int e = beg;
    for (; e + 1 < end; e += 2) {
        int s0 = g_csr_src[e], s1 = g_csr_src[e + 1];
        float n0 = g_norm_src[s0], n1 = g_norm_src[s1];
        unsigned long long u0 = h8[s0 * 32 + lane];
        unsigned long long u1 = h8[s1 * 32 + lane];
        __half2 a0 = *(__half2*)&u0, b0 = *((__half2*)&u0 + 1);
        __half2 a1 = *(__half2*)&u1, b1 = *((__half2*)&u1 + 1);
        float2 f00 = __half22float2(a0), f01 = __half22float2(b0);
        float2 f10 = __half22float2(a1), f11 = __half22float2(b1);
        acc.x = fmaf(n0, f00.x, acc.x); acc.y = fmaf(n0, f00.y, acc.y);
        acc.z = fmaf(n0, f01.x, acc.z); acc.w = fmaf(n0, f01.y, acc.w);
        acc.x = fmaf(n1, f10.x, acc.x); acc.y = fmaf(n1, f10.y, acc.y);
        acc.z = fmaf(n1, f11.x, acc.z); acc.w = fmaf(n1, f11.y, acc.w);
    }
    if (e < end) {
        int s = g_csr_src[e];
        float ns = g_norm_src[s];
        unsigned long long u = h8[s * 32 + lane];
        __half2 a = *(__half2*)&u, b = *((__half2*)&u + 1);
        float2 f0 = __half22float2(a), f1 = __half22float2(b);
        acc.x = fmaf(ns, f0.x, acc.x); acc.y = fmaf(ns, f0.y, acc.y);
        acc.z = fmaf(ns, f1.x, acc.z); acc.w = fmaf(ns, f1.y, acc.w);
    }
    float nd = g_norm_dst[node];
    ((float4*)g_agg)[node * 32 + lane] =
        make_float4(acc.x * nd, acc.y * nd, acc.z * nd, acc.w * nd);
}

// ---------------- fused GEMM (f32x2) + bias + leaky + dropout --------------
// A = g_agg (symbol). DEST=0 -> fp16 to g_hh; DEST=1 -> fp32 to out_param.
template <int NOUT, int TN, int DEST>
__global__ __launch_bounds__(256)
void gemm_fused_kernel(const float* __restrict__ Wm,
                       const float* __restrict__ bias,
                       int mask_off,
                       float* __restrict__ out_param) {
    __align__(16) __shared__ float sAT[32][132];
    __align__(16) __shared__ float sB[32][NOUT];
    int t = threadIdx.x;
    int block_row = blockIdx.x * 128;
    int tx = t & 15, ty = t >> 4;

    unsigned long long accP[8][TN / 2];
#pragma unroll
    for (int i = 0; i < 8; i++)
#pragma unroll
        for (int j = 0; j < TN / 2; j++) accP[i][j] = 0ull;

    const float4* A4 = (const float4*)g_agg;
    const float4* W4 = (const float4*)Wm;

#pragma unroll 1
    for (int kt = 0; kt < 4; kt++) {
#pragma unroll
        for (int i = 0; i < 4; i++) {
            int f4 = t + i * 256;
            int row = f4 >> 3, c4 = f4 & 7;
            int gr = block_row + row;
            float4 v = (gr < NNODES) ? A4[gr * 32 + kt * 8 + c4]
                                     : make_float4(0.f, 0.f, 0.f, 0.f);
            int k0 = c4 * 4;
            sAT[k0 + 0][row] = v.x;
            sAT[k0 + 1][row] = v.y;
            sAT[k0 + 2][row] = v.z;
            sAT[k0 + 3][row] = v.w;
        }
        constexpr int WB4 = 32 * NOUT / 4;
#pragma unroll
        for (int i = 0; i < WB4 / 256; i++) {
            int f4 = t + i * 256;
            int kr = f4 / (NOUT / 4), c4 = f4 % (NOUT / 4);
            ((float4*)&sB[kr][0])[c4] = W4[(kt * 32 + kr) * (NOUT / 4) + c4];
        }
        __syncthreads();
#pragma unroll
        for (int k = 0; k < 32; k++) {
            float a[8];
            *(float4*)&a[0] = *(const float4*)&sAT[k][ty * 8];
            *(float4*)&a[4] = *(const float4*)&sAT[k][ty * 8 + 4];
            unsigned long long av[8];
#pragma unroll
            for (int i = 0; i < 8; i++) av[i] = pack2(a[i], a[i]);
            float b[TN];
#pragma unroll
            for (int j4 = 0; j4 < TN / 4; j4++)
                *(float4*)&b[j4 * 4] = *(const float4*)&sB[k][tx * TN + j4 * 4];
            unsigned long long bv[TN / 2];
#pragma unroll
            for (int j = 0; j < TN / 2; j++) bv[j] = pack2(b[2 * j], b[2 * j + 1]);
#pragma unroll
            for (int i = 0; i < 8; i++)
#pragma unroll
                for (int j = 0; j < TN / 2; j++)
                    fma2(accP[i][j], av[i], bv[j]);
        }
        __syncthreads();
    }

    const unsigned* mask = g_mask + mask_off;
#pragma unroll
    for (int i = 0; i < 8; i++) {
        int gr = block_row + ty * 8 + i;
        if (gr >= NNODES) continue;
        unsigned base = (unsigned)(gr * NOUT + tx * TN);
        unsigned mb = mask[base >> 5] >> (base & 31);
        float vv[TN];
#pragma unroll
        for (int j = 0; j < TN / 2; j++)
            unpack2(accP[i][j], vv[2 * j], vv[2 * j + 1]);
#pragma unroll
        for (int j = 0; j < TN; j++) {
            float v = vv[j] + bias[tx * TN + j];
            v = (v >= 0.f) ? v : 0.01f * v;
            vv[j] = ((mb >> j) & 1u) ? v * 2.f : 0.f;
        }
        if (DEST == 0) {
            uint4 u;
            __half2 p0 = __floats2half2_rn(vv[0], vv[1]);
            __half2 p1 = __floats2half2_rn(vv[2], vv[3]);
            __half2 p2 = __floats2half2_rn(vv[4], vv[5]);
            __half2 p3 = __floats2half2_rn(vv[6], vv[7]);
            u.x = *(unsigned*)&p0; u.y = *(unsigned*)&p1;
            u.z = *(unsigned*)&p2; u.w = *(unsigned*)&p3;
            *(uint4*)&g_hh[base] = u;
        } else {
#pragma unroll
            for (int j = 0; j < TN; j++) out_param[base + j] = vv[j];
        }
    }
}

// ---------------- host launch ----------------
extern "C" void kernel_launch(void* const* d_in, const int* in_sizes, int n_in,
                              void* d_out, int out_size) {
    // bind inputs by size signature (validated R13)
    int iF = -1, iE1 = -1, iE2 = -1, iW1 = -1, iW2 = -1, iW3 = -1;
    int iB1 = -1, iB2 = -1, iB3 = -1;
    for (int i = 0; i < n_in; i++) {
        int s = in_sizes[i];
        if (s == 16384)      { if (iW1 < 0) iW1 = i; else iW2 = i; }
        else if (s == 8192)  iW3 = i;
        else if (s == 128)   { if (iB1 < 0) iB1 = i; else iB2 = i; }
        else if (s == 64)    iB3 = i;
        else if (s == 800000 || s == 1600000) { if (iE1 < 0) iE1 = i; else iE2 = i; }
        else if (s == 6400000) iF = i;
    }
    bool matched = (iF >= 0 && iE1 >= 0 && iE2 >= 0 && iW1 >= 0 && iW2 >= 0 &&
                    iW3 >= 0 && iB1 >= 0 && iB2 >= 0 && iB3 >= 0);
    int iSrc, iDst;
    if (matched) { if (iF < iE1) { iSrc = iE1; iDst = iE2; }
                   else          { iDst = iE1; iSrc = iE2; } }
    else { iF = 0; iSrc = 1; iDst = 2; iW1 = 3; iB1 = 4; iW2 = 5; iB2 = 6;
           iW3 = 7; iB3 = 8; }

    const float* features = (const float*)d_in[iF];
    const void*  src      = d_in[iSrc];
    const void*  dst      = d_in[iDst];
    const float* W1 = (const float*)d_in[iW1];
    const float* b1 = (const float*)d_in[iB1];
    const float* W2 = (const float*)d_in[iW2];
    const float* b2 = (const float*)d_in[iB2];
    const float* W3 = (const float*)d_in[iW3];
    const float* b3 = (const float*)d_in[iB3];
    float* out = (float*)d_out;

    unsigned dk[3][2];
    for (unsigned i = 0; i < 3; i++) tf2x32(0u, 42u, 0u, i, dk[i][0], dk[i][1]);

    const int EB = (NEDGES + 255) / 256;
    const int NB = (NNODES + 255) / 256;
    const int AB = (NNODES * 32 + 255) / 256;
    const int GB = (NNODES + 127) / 128;
    const int CB = (NNODES * 32 + 255) / 256;

    detect_zero_kernel<<<NB, 256>>>(src);
    degrees_kernel<<<EB, 256>>>(src, dst);
    norms_kernel<<<NB, 256>>>();
    scan_kernel<<<1, 1024>>>();
    scatter_kernel<<<EB, 256>>>(src, dst);
    f2h_kernel<<<CB, 256>>>(features);

    aggregate_kernel<128><<<AB, 256>>>(dk[0][0], dk[0][1], MOFF_L1);
    gemm_fused_kernel<128, 8, 0><<<GB, 256>>>(W1, b1, MOFF_L1, nullptr);

    aggregate_kernel<128><<<AB, 256>>>(dk[1][0], dk[1][1], MOFF_L2);
    gemm_fused_kernel<128, 8, 0><<<GB, 256>>>(W2, b2, MOFF_L2, nullptr);

    aggregate_kernel<64><<<AB, 256>>>(dk[2][0], dk[2][1], MOFF_L3);
    gemm_fused_kernel<64, 4, 1><<<GB, 256>>>(W3, b3, MOFF_L3, out);

    (void)out_size;
}

// round 17
// speedup vs baseline: 1.5797x; 1.5797x over previous
#include <cuda_runtime.h>
#include <cuda_fp16.h>
#include <cstdint>

#define NNODES 50000
#define NEDGES 800000

#define MASK_WORDS 500000
#define MOFF_L1 0
#define MOFF_L2 200000
#define MOFF_L3 400000

#define SCAN_BLOCKS 49   // 49 * 1024 = 50176 >= NNODES

// ---------------- device scratch (symbols ONLY ever touched in device code) --
__device__ __align__(16) int    g_mode;
__device__ __align__(16) int    g_deg_out[NNODES];
__device__ __align__(16) int    g_deg_in[NNODES];
__device__ __align__(16) int    g_fill[NNODES];
__device__ __align__(16) int    g_rowptr[NNODES + 1];
__device__ __align__(16) int    g_blocksum[SCAN_BLOCKS];
__device__ __align__(16) int    g_blockoff[SCAN_BLOCKS];
__device__ __align__(16) int    g_csr_src[NEDGES];
__device__ __align__(16) float  g_norm_src[NNODES];
__device__ __align__(16) float  g_norm_dst[NNODES];
__device__ __align__(16) float  g_agg[NNODES * 128];   // fp32 GEMM input
__device__ __align__(16) __half g_hh[NNODES * 128];    // fp16 gather operand
__device__ __align__(16) unsigned g_mask[MASK_WORDS];

// ---------------- f32x2 packed math ----------------
__device__ __forceinline__ unsigned long long pack2(float x, float y) {
    unsigned long long r;
    asm("mov.b64 %0, {%1, %2};" : "=l"(r) : "f"(x), "f"(y));
    return r;
}
__device__ __forceinline__ void unpack2(unsigned long long v, float& x, float& y) {
    asm("mov.b64 {%0, %1}, %2;" : "=f"(x), "=f"(y) : "l"(v));
}
__device__ __forceinline__ void fma2(unsigned long long& d,
                                     unsigned long long a, unsigned long long b) {
    asm("fma.rn.f32x2 %0, %1, %2, %0;" : "+l"(d) : "l"(a), "l"(b));
}

// ---------------- threefry-2x32 ----------------
__host__ __device__ __forceinline__ void tf2x32(unsigned k0, unsigned k1,
                                                unsigned x0, unsigned x1,
                                                unsigned& o0, unsigned& o1) {
    unsigned ks2 = k0 ^ k1 ^ 0x1BD11BDAu;
#define TF_R(r) do { x0 += x1; x1 = (x1 << (r)) | (x1 >> (32 - (r))); x1 ^= x0; } while (0)
    x0 += k0; x1 += k1;
    TF_R(13); TF_R(15); TF_R(26); TF_R(6);   x0 += k1;  x1 += ks2 + 1u;
    TF_R(17); TF_R(29); TF_R(16); TF_R(24);  x0 += ks2; x1 += k0 + 2u;
    TF_R(13); TF_R(15); TF_R(26); TF_R(6);   x0 += k0;  x1 += k1 + 3u;
    TF_R(17); TF_R(29); TF_R(16); TF_R(24);  x0 += k1;  x1 += ks2 + 4u;
    TF_R(13); TF_R(15); TF_R(26); TF_R(6);   x0 += ks2; x1 += k0 + 5u;
#undef TF_R
    o0 = x0; o1 = x1;
}

// JAX partitionable dropout mask (validated R13)
__global__ void mask_kernel(unsigned k0, unsigned k1, int offw, int nwords) {
    int w = blockIdx.x * blockDim.x + threadIdx.x;
    if (w >= nwords) return;
    unsigned m = 0u;
    int base = w << 5;
#pragma unroll 4
    for (int b = 0; b < 32; b++) {
        unsigned o0, o1;
        tf2x32(k0, k1, 0u, (unsigned)(base + b), o0, o1);
        m |= (unsigned)(!((o0 ^ o1) >> 31)) << b;
    }
    g_mask[offw + w] = m;
}

// ---------------- edge dtype detect ----------------
__global__ void detect_kernel(const void* src) {
    const unsigned* w = (const unsigned*)src;
    int odd_nonzero = 0, hi16 = 0;
    for (int i = 0; i < 256; i += 2) {
        if (w[i + 1] != 0u) odd_nonzero++;
        if (w[i] & 0xFFFF0000u) hi16++;
    }
    if (odd_nonzero == 0) g_mode = 1;
    else if (hi16 > 64)   g_mode = 2;
    else                  g_mode = 0;
}

__device__ __forceinline__ int edge_val(const void* p, int i) {
    int v;
    if (g_mode == 1)      v = (int)((const long long*)p)[i];
    else if (g_mode == 2) v = (int)((const float*)p)[i];
    else                  v = ((const int*)p)[i];
    v = v < 0 ? 0 : v;
    return v >= NNODES ? NNODES - 1 : v;
}

// ---------------- preprocessing ----------------
__global__ void zero_kernel() {
    int i = blockIdx.x * blockDim.x + threadIdx.x;
    if (i < NNODES) { g_deg_out[i] = 0; g_deg_in[i] = 0; g_fill[i] = 0; }
}

__global__ void degrees_kernel(const void* src, const void* dst) {
    int e = blockIdx.x * blockDim.x + threadIdx.x;
    if (e < NEDGES) {
        atomicAdd(&g_deg_out[edge_val(src, e)], 1);
        atomicAdd(&g_deg_in[edge_val(dst, e)], 1);
    }
}

__global__ void norms_kernel() {
    int i = blockIdx.x * blockDim.x + threadIdx.x;
    if (i < NNODES) {
        float dO = (float)g_deg_out[i];
        float dI = (float)g_deg_in[i];
        g_norm_src[i] = rsqrtf(dO > 1.0f ? dO : 1.0f);
        g_norm_dst[i] = rsqrtf(dI > 1.0f ? dI : 1.0f);
    }
}

// ---- multi-block scan, phase 1: block-local exclusive scan + block totals --
__global__ void scan1_kernel() {
    __shared__ int warp_sums[32];
    int t = threadIdx.x, lane = t & 31, wid = t >> 5;
    int i = blockIdx.x * 1024 + t;
    int v = (i < NNODES) ? g_deg_in[i] : 0;
    int val = v;
#pragma unroll
    for (int off = 1; off < 32; off <<= 1) {
        int n = __shfl_up_sync(0xFFFFFFFFu, val, off);
        if (lane >= off) val += n;
    }
    if (lane == 31) warp_sums[wid] = val;
    __syncthreads();
    if (wid == 0) {
        int s = warp_sums[lane];
#pragma unroll
        for (int off = 1; off < 32; off <<= 1) {
            int n = __shfl_up_sync(0xFFFFFFFFu, s, off);
            if (lane >= off) s += n;
        }
        warp_sums[lane] = s;
    }
    __syncthreads();
    int prefix = (wid > 0 ? warp_sums[wid - 1] : 0);
    if (i < NNODES) g_rowptr[i] = prefix + val - v;   // exclusive, block-local
    if (t == 1023) g_blocksum[blockIdx.x] = prefix + val;
}

// ---- phase 2: scan the 49 block totals (tiny) --------------------------
__global__ void scan2_kernel() {
    __shared__ int s[SCAN_BLOCKS];
    int t = threadIdx.x;
    if (t < SCAN_BLOCKS) s[t] = g_blocksum[t];
    __syncthreads();
    if (t == 0) {
        int run = 0;
#pragma unroll 1
        for (int b = 0; b < SCAN_BLOCKS; b++) {
            g_blockoff[b] = run;
            run += s[b];
        }
        g_rowptr[NNODES] = run;
    }
}

// ---- phase 3: add block offsets ---------------------------------------
__global__ void scan3_kernel() {
    int i = blockIdx.x * blockDim.x + threadIdx.x;
    if (i < NNODES) g_rowptr[i] += g_blockoff[i >> 10];
}

__global__ void scatter_kernel(const void* src, const void* dst) {
    int e = blockIdx.x * blockDim.x + threadIdx.x;
    if (e < NEDGES) {
        int d = edge_val(dst, e);
        int pos = g_rowptr[d] + atomicAdd(&g_fill[d], 1);
        if (pos >= 0 && pos < NEDGES) g_csr_src[pos] = edge_val(src, e);
    }
}

// ---------------- features fp32 -> fp16 ----------------
__global__ void f2h_kernel(const float* __restrict__ x) {
    int i = blockIdx.x * blockDim.x + threadIdx.x;   // over float4s
    if (i >= NNODES * 32) return;
    float4 v = ((const float4*)x)[i];
    __half2 p0 = __floats2half2_rn(v.x, v.y);
    __half2 p1 = __floats2half2_rn(v.z, v.w);
    unsigned long long u;
    asm("mov.b64 %0, {%1, %2};" : "=l"(u)
        : "r"(*(unsigned*)&p0), "r"(*(unsigned*)&p1));
    ((unsigned long long*)g_hh)[i] = u;
}

// ---------------- aggregation: warp per node, fp16 gather, fp32 accum ------
__global__ void aggregate_kernel() {
    int gtid = blockIdx.x * blockDim.x + threadIdx.x;
    int node = gtid >> 5;
    int lane = gtid & 31;
    if (node >= NNODES) return;
    const unsigned long long* h8 = (const unsigned long long*)g_hh;
    int beg = g_rowptr[node], end = g_rowptr[node + 1];
    float4 acc = make_float4(0.f, 0.f, 0.f, 0.f);
    int e = beg;
    for (; e + 1 < end; e += 2) {
        int s0 = g_csr_src[e], s1 = g_csr_src[e + 1];
        float n0 = g_norm_src[s0], n1 = g_norm_src[s1];
        unsigned long long u0 = h8[s0 * 32 + lane];
        unsigned long long u1 = h8[s1 * 32 + lane];
        __half2 a0 = *(__half2*)&u0, b0 = *((__half2*)&u0 + 1);
        __half2 a1 = *(__half2*)&u1, b1 = *((__half2*)&u1 + 1);
        float2 f00 = __half22float2(a0), f01 = __half22float2(b0);
        float2 f10 = __half22float2(a1), f11 = __half22float2(b1);
        acc.x = fmaf(n0, f00.x, acc.x); acc.y = fmaf(n0, f00.y, acc.y);
        acc.z = fmaf(n0, f01.x, acc.z); acc.w = fmaf(n0, f01.y, acc.w);
        acc.x = fmaf(n1, f10.x, acc.x); acc.y = fmaf(n1, f10.y, acc.y);
        acc.z = fmaf(n1, f11.x, acc.z); acc.w = fmaf(n1, f11.y, acc.w);
    }
    if (e < end) {
        int s = g_csr_src[e];
        float ns = g_norm_src[s];
        unsigned long long u = h8[s * 32 + lane];
        __half2 a = *(__half2*)&u, b = *((__half2*)&u + 1);
        float2 f0 = __half22float2(a), f1 = __half22float2(b);
        acc.x = fmaf(ns, f0.x, acc.x); acc.y = fmaf(ns, f0.y, acc.y);
        acc.z = fmaf(ns, f1.x, acc.z); acc.w = fmaf(ns, f1.y, acc.w);
    }
    float nd = g_norm_dst[node];
    ((float4*)g_agg)[node * 32 + lane] =
        make_float4(acc.x * nd, acc.y * nd, acc.z * nd, acc.w * nd);
}

// ---------------- fused GEMM (f32x2) + bias + leaky + dropout --------------
// A = g_agg (symbol). DEST=0 -> fp16 to g_hh; DEST=1 -> fp32 to out_param.
template <int NOUT, int TN, int DEST>
__global__ __launch_bounds__(256)
void gemm_fused_kernel(const float* __restrict__ Wm,
                       const float* __restrict__ bias,
                       int mask_off,
                       float* __restrict__ out_param) {
    __align__(16) __shared__ float sAT[32][132];
    __align__(16) __shared__ float sB[32][NOUT];
    int t = threadIdx.x;
    int block_row = blockIdx.x * 128;
    int tx = t & 15, ty = t >> 4;

    unsigned long long accP[8][TN / 2];
#pragma unroll
    for (int i = 0; i < 8; i++)
#pragma unroll
        for (int j = 0; j < TN / 2; j++) accP[i][j] = 0ull;

    const float4* A4 = (const float4*)g_agg;
    const float4* W4 = (const float4*)Wm;

#pragma unroll 1
    for (int kt = 0; kt < 4; kt++) {
#pragma unroll
        for (int i = 0; i < 4; i++) {
            int f4 = t + i * 256;
            int row = f4 >> 3, c4 = f4 & 7;
            int gr = block_row + row;
            float4 v = (gr < NNODES) ? A4[gr * 32 + kt * 8 + c4]
                                     : make_float4(0.f, 0.f, 0.f, 0.f);
            int k0 = c4 * 4;
            sAT[k0 + 0][row] = v.x;
            sAT[k0 + 1][row] = v.y;
            sAT[k0 + 2][row] = v.z;
            sAT[k0 + 3][row] = v.w;
        }
        constexpr int WB4 = 32 * NOUT / 4;
#pragma unroll
        for (int i = 0; i < WB4 / 256; i++) {
            int f4 = t + i * 256;
            int kr = f4 / (NOUT / 4), c4 = f4 % (NOUT / 4);
            ((float4*)&sB[kr][0])[c4] = W4[(kt * 32 + kr) * (NOUT / 4) + c4];
        }
        __syncthreads();
#pragma unroll
        for (int k = 0; k < 32; k++) {
            float a[8];
            *(float4*)&a[0] = *(const float4*)&sAT[k][ty * 8];
            *(float4*)&a[4] = *(const float4*)&sAT[k][ty * 8 + 4];
            unsigned long long av[8];
#pragma unroll
            for (int i = 0; i < 8; i++) av[i] = pack2(a[i], a[i]);
            float b[TN];
#pragma unroll
            for (int j4 = 0; j4 < TN / 4; j4++)
                *(float4*)&b[j4 * 4] = *(const float4*)&sB[k][tx * TN + j4 * 4];
            unsigned long long bv[TN / 2];
#pragma unroll
            for (int j = 0; j < TN / 2; j++) bv[j] = pack2(b[2 * j], b[2 * j + 1]);
#pragma unroll
            for (int i = 0; i < 8; i++)
#pragma unroll
                for (int j = 0; j < TN / 2; j++)
                    fma2(accP[i][j], av[i], bv[j]);
        }
        __syncthreads();
    }

    const unsigned* mask = g_mask + mask_off;
#pragma unroll
    for (int i = 0; i < 8; i++) {
        int gr = block_row + ty * 8 + i;
        if (gr >= NNODES) continue;
        unsigned base = (unsigned)(gr * NOUT + tx * TN);
        unsigned mb = mask[base >> 5] >> (base & 31);
        float vv[TN];
#pragma unroll
        for (int j = 0; j < TN / 2; j++)
            unpack2(accP[i][j], vv[2 * j], vv[2 * j + 1]);
#pragma unroll
        for (int j = 0; j < TN; j++) {
            float v = vv[j] + bias[tx * TN + j];
            v = (v >= 0.f) ? v : 0.01f * v;
            vv[j] = ((mb >> j) & 1u) ? v * 2.f : 0.f;
        }
        if (DEST == 0) {
            uint4 u;
            __half2 p0 = __floats2half2_rn(vv[0], vv[1]);
            __half2 p1 = __floats2half2_rn(vv[2], vv[3]);
            __half2 p2 = __floats2half2_rn(vv[4], vv[5]);
            __half2 p3 = __floats2half2_rn(vv[6], vv[7]);
            u.x = *(unsigned*)&p0; u.y = *(unsigned*)&p1;
            u.z = *(unsigned*)&p2; u.w = *(unsigned*)&p3;
            *(uint4*)&g_hh[base] = u;
        } else {
#pragma unroll
            for (int j = 0; j < TN; j++) out_param[base + j] = vv[j];
        }
    }
}

// ---------------- host launch ----------------
extern "C" void kernel_launch(void* const* d_in, const int* in_sizes, int n_in,
                              void* d_out, int out_size) {
    // bind inputs by size signature (validated R13)
    int iF = -1, iE1 = -1, iE2 = -1, iW1 = -1, iW2 = -1, iW3 = -1;
    int iB1 = -1, iB2 = -1, iB3 = -1;
    for (int i = 0; i < n_in; i++) {
        int s = in_sizes[i];
        if (s == 16384)      { if (iW1 < 0) iW1 = i; else iW2 = i; }
        else if (s == 8192)  iW3 = i;
        else if (s == 128)   { if (iB1 < 0) iB1 = i; else iB2 = i; }
        else if (s == 64)    iB3 = i;
        else if (s == 800000 || s == 1600000) { if (iE1 < 0) iE1 = i; else iE2 = i; }
        else if (s == 6400000) iF = i;
    }
    bool matched = (iF >= 0 && iE1 >= 0 && iE2 >= 0 && iW1 >= 0 && iW2 >= 0 &&
                    iW3 >= 0 && iB1 >= 0 && iB2 >= 0 && iB3 >= 0);
    int iSrc, iDst;
    if (matched) { if (iF < iE1) { iSrc = iE1; iDst = iE2; }
                   else          { iDst = iE1; iSrc = iE2; } }
    else { iF = 0; iSrc = 1; iDst = 2; iW1 = 3; iB1 = 4; iW2 = 5; iB2 = 6;
           iW3 = 7; iB3 = 8; }

    const float* features = (const float*)d_in[iF];
    const void*  src      = d_in[iSrc];
    const void*  dst      = d_in[iDst];
    const float* W1 = (const float*)d_in[iW1];
    const float* b1 = (const float*)d_in[iB1];
    const float* W2 = (const float*)d_in[iW2];
    const float* b2 = (const float*)d_in[iB2];
    const float* W3 = (const float*)d_in[iW3];
    const float* b3 = (const float*)d_in[iB3];
    float* out = (float*)d_out;

    unsigned dk[3][2];
    for (unsigned i = 0; i < 3; i++) tf2x32(0u, 42u, 0u, i, dk[i][0], dk[i][1]);

    const int EB = (NEDGES + 255) / 256;
    const int NB = (NNODES + 255) / 256;
    const int AB = (NNODES * 32 + 255) / 256;
    const int GB = (NNODES + 127) / 128;
    const int CB = (NNODES * 32 + 255) / 256;

    detect_kernel<<<1, 1>>>(src);
    zero_kernel<<<NB, 256>>>();
    degrees_kernel<<<EB, 256>>>(src, dst);
    norms_kernel<<<NB, 256>>>();
    scan1_kernel<<<SCAN_BLOCKS, 1024>>>();
    scan2_kernel<<<1, 64>>>();
    scan3_kernel<<<NB, 256>>>();
    scatter_kernel<<<EB, 256>>>(src, dst);

    mask_kernel<<<(200000 + 255) / 256, 256>>>(dk[0][0], dk[0][1], MOFF_L1, 200000);
    mask_kernel<<<(200000 + 255) / 256, 256>>>(dk[1][0], dk[1][1], MOFF_L2, 200000);
    mask_kernel<<<(100000 + 255) / 256, 256>>>(dk[2][0], dk[2][1], MOFF_L3, 100000);

    f2h_kernel<<<CB, 256>>>(features);

    aggregate_kernel<<<AB, 256>>>();
    gemm_fused_kernel<128, 8, 0><<<GB, 256>>>(W1, b1, MOFF_L1, nullptr);

    aggregate_kernel<<<AB, 256>>>();
    gemm_fused_kernel<128, 8, 0><<<GB, 256>>>(W2, b2, MOFF_L2, nullptr);

    aggregate_kernel<<<AB, 256>>>();
    gemm_fused_kernel<64, 4, 1><<<GB, 256>>>(W3, b3, MOFF_L3, out);

    (void)out_size;
}